// round 5
// baseline (speedup 1.0000x reference)
#include <cuda_runtime.h>
#include <cstdint>
#include <math.h>

#define LL 512
#define CC 128
#define NROWS (LL*LL)   // 262144

// ---- scratch ----
__device__ float g_X[NROWS*CC];     // normalized input (n-major); reused for normalized einsum out
__device__ float g_Lt[CC*NROWS];    // left  gated+masked, c-major planes [c][i*512+k], tf32-rounded
__device__ float g_Rt[CC*NROWS];    // right gated+masked, c-major planes [c][j*512+k], tf32-rounded
__device__ float g_Fg[NROWS*CC];    // sigmoid(final gate), n-major
__device__ float g_Ot[CC*NROWS];    // einsum output, c-major planes [c][i*512+j]

__device__ __forceinline__ float sigf(float x) {
    return 1.0f / (1.0f + __expf(-x));
}
__device__ __forceinline__ float tf32r(float x) {
    uint32_t y;
    asm("cvt.rna.tf32.f32 %0, %1;" : "=r"(y) : "f"(x));
    return __uint_as_float(y);
}
__device__ __forceinline__ void mma_tf32(float* c, const uint32_t* a, const uint32_t* b) {
    asm volatile(
        "mma.sync.aligned.m16n8k8.row.col.f32.tf32.tf32.f32 "
        "{%0,%1,%2,%3}, {%4,%5,%6,%7}, {%8,%9}, {%0,%1,%2,%3};"
        : "+f"(c[0]), "+f"(c[1]), "+f"(c[2]), "+f"(c[3])
        : "r"(a[0]), "r"(a[1]), "r"(a[2]), "r"(a[3]), "r"(b[0]), "r"(b[1]));
}

// ---------------- LayerNorm: one warp per row of 128 ----------------
__global__ void ln_kernel(const float* __restrict__ in,
                          const float* __restrict__ scale,
                          const float* __restrict__ bias,
                          float* __restrict__ out)
{
    int warp = (blockIdx.x * blockDim.x + threadIdx.x) >> 5;
    int lane = threadIdx.x & 31;
    if (warp >= NROWS) return;
    const float4 v = *(const float4*)(in + (size_t)warp * CC + lane * 4);
    float s  = v.x + v.y + v.z + v.w;
    float sq = v.x*v.x + v.y*v.y + v.z*v.z + v.w*v.w;
    #pragma unroll
    for (int o = 16; o > 0; o >>= 1) {
        s  += __shfl_xor_sync(0xffffffffu, s,  o);
        sq += __shfl_xor_sync(0xffffffffu, sq, o);
    }
    float mean = s * (1.0f / CC);
    float var  = sq * (1.0f / CC) - mean * mean;
    float rstd = rsqrtf(var + 1e-5f);
    float4 sc = *(const float4*)(scale + lane * 4);
    float4 bi = *(const float4*)(bias  + lane * 4);
    float4 r;
    r.x = (v.x - mean) * rstd * sc.x + bi.x;
    r.y = (v.y - mean) * rstd * sc.y + bi.y;
    r.z = (v.z - mean) * rstd * sc.z + bi.z;
    r.w = (v.w - mean) * rstd * sc.w + bi.w;
    *(float4*)(out + (size_t)warp * CC + lane * 4) = r;
}

// ---------------- single-weight tf32 GEMM: (N x 128) @ (128 x 128) ----------------
// mode 0: out = acc + bias
// mode 1: out = (acc + bias) * gate
// mode 2: out = sigmoid(acc + bias)
__global__ void __launch_bounds__(256) gemm_mma_s(
    const float* __restrict__ X,
    const float* __restrict__ W,
    const float* __restrict__ B,
    float* __restrict__ out,
    const float* __restrict__ gate,
    int mode)
{
    __shared__ float Xs[128 * 20];
    __shared__ float Ws[16 * 136];
    const int r0   = blockIdx.x * 128;
    const int tid  = threadIdx.x;
    const int wid  = tid >> 5;
    const int lane = tid & 31;
    const int warp_m = wid >> 2;
    const int warp_n = wid & 3;
    const int lr = lane >> 2;
    const int lc = lane & 3;

    float acc[16][4];
    #pragma unroll
    for (int t = 0; t < 16; t++)
        #pragma unroll
        for (int q = 0; q < 4; q++) acc[t][q] = 0.0f;

    for (int k0 = 0; k0 < CC; k0 += 16) {
        #pragma unroll
        for (int u = 0; u < 2; u++) {
            int idx = tid + u * 256;
            int r = idx >> 2;
            int q = idx & 3;
            float4 v = *(const float4*)(X + (size_t)(r0 + r) * CC + k0 + q * 4);
            v.x = tf32r(v.x); v.y = tf32r(v.y); v.z = tf32r(v.z); v.w = tf32r(v.w);
            *(float4*)(&Xs[r * 20 + q * 4]) = v;
        }
        #pragma unroll
        for (int u = 0; u < 2; u++) {
            int idx = tid + u * 256;
            int k = idx >> 5;
            int q = idx & 31;
            float4 v = *(const float4*)(W + (size_t)(k0 + k) * CC + q * 4);
            v.x = tf32r(v.x); v.y = tf32r(v.y); v.z = tf32r(v.z); v.w = tf32r(v.w);
            *(float4*)(&Ws[k * 136 + q * 4]) = v;
        }
        __syncthreads();
        #pragma unroll
        for (int ks = 0; ks < 16; ks += 8) {
            uint32_t a[4][4], b[4][2];
            #pragma unroll
            for (int mt = 0; mt < 4; mt++) {
                int rb = (warp_m * 64 + mt * 16 + lr) * 20 + ks + lc;
                a[mt][0] = __float_as_uint(Xs[rb]);
                a[mt][1] = __float_as_uint(Xs[rb + 8 * 20]);
                a[mt][2] = __float_as_uint(Xs[rb + 4]);
                a[mt][3] = __float_as_uint(Xs[rb + 8 * 20 + 4]);
            }
            #pragma unroll
            for (int nt = 0; nt < 4; nt++) {
                int nb = warp_n * 32 + nt * 8 + lr;
                b[nt][0] = __float_as_uint(Ws[(ks + lc) * 136 + nb]);
                b[nt][1] = __float_as_uint(Ws[(ks + 4 + lc) * 136 + nb]);
            }
            #pragma unroll
            for (int mt = 0; mt < 4; mt++)
                #pragma unroll
                for (int nt = 0; nt < 4; nt++)
                    mma_tf32(acc[mt * 4 + nt], a[mt], b[nt]);
        }
        __syncthreads();
    }

    #pragma unroll
    for (int mt = 0; mt < 4; mt++) {
        #pragma unroll
        for (int nt = 0; nt < 4; nt++) {
            int col = warp_n * 32 + nt * 8 + lc * 2;
            float2 bb = *(const float2*)(B + col);
            #pragma unroll
            for (int h = 0; h < 2; h++) {
                int row = r0 + warp_m * 64 + mt * 16 + lr + h * 8;
                float2 v;
                v.x = acc[mt * 4 + nt][h * 2 + 0] + bb.x;
                v.y = acc[mt * 4 + nt][h * 2 + 1] + bb.y;
                if (mode == 1) {
                    float2 gv = *(const float2*)(gate + (size_t)row * CC + col);
                    v.x *= gv.x; v.y *= gv.y;
                } else if (mode == 2) {
                    v.x = sigf(v.x); v.y = sigf(v.y);
                }
                *(float2*)(out + (size_t)row * CC + col) = v;
            }
        }
    }
}

// ---------------- fused projection + gate + mask + c-major transpose ----------------
// blockIdx.y: 0 -> (w_left, w_lgate) -> g_Lt ; 1 -> (w_right, w_rgate) -> g_Rt
// Computes v = (X@W + b) * pair_mask * sigmoid(X@Wg + bg), tf32-rounded, written c-major.
__global__ void __launch_bounds__(256) proj_lr(
    const float* __restrict__ X,
    const float* __restrict__ w_l,  const float* __restrict__ w_lg,
    const float* __restrict__ b_l,  const float* __restrict__ b_lg,
    const float* __restrict__ w_r,  const float* __restrict__ w_rg,
    const float* __restrict__ b_r,  const float* __restrict__ b_rg,
    const float* __restrict__ mask)
{
    __shared__ float sbuf[64 * 132];   // epilogue tile (33.8KB) >= mainloop 6912 floats
    float* Xs  = sbuf;                 // 128*20 = 2560
    float* Ws  = sbuf + 2560;          // 16*136 = 2176
    float* Wgs = sbuf + 2560 + 2176;   // 16*136

    const int sel = blockIdx.y;
    const float* W  = sel ? w_r  : w_l;
    const float* Wg = sel ? w_rg : w_lg;
    const float* B  = sel ? b_r  : b_l;
    const float* Bg = sel ? b_rg : b_lg;
    float* dstT = sel ? g_Rt : g_Lt;

    const int n0   = blockIdx.x * 128;
    const int tid  = threadIdx.x;
    const int wid  = tid >> 5;
    const int lane = tid & 31;
    const int warp_m = wid >> 2;
    const int warp_n = wid & 3;
    const int lr = lane >> 2;
    const int lc = lane & 3;

    float acc[16][4], accg[16][4];
    #pragma unroll
    for (int t = 0; t < 16; t++)
        #pragma unroll
        for (int q = 0; q < 4; q++) { acc[t][q] = 0.0f; accg[t][q] = 0.0f; }

    for (int k0 = 0; k0 < CC; k0 += 16) {
        #pragma unroll
        for (int u = 0; u < 2; u++) {
            int idx = tid + u * 256;
            int r = idx >> 2;
            int q = idx & 3;
            float4 v = *(const float4*)(X + (size_t)(n0 + r) * CC + k0 + q * 4);
            v.x = tf32r(v.x); v.y = tf32r(v.y); v.z = tf32r(v.z); v.w = tf32r(v.w);
            *(float4*)(&Xs[r * 20 + q * 4]) = v;
        }
        #pragma unroll
        for (int u = 0; u < 2; u++) {
            int idx = tid + u * 256;
            int k = idx >> 5;
            int q = idx & 31;
            float4 v = *(const float4*)(W + (size_t)(k0 + k) * CC + q * 4);
            v.x = tf32r(v.x); v.y = tf32r(v.y); v.z = tf32r(v.z); v.w = tf32r(v.w);
            *(float4*)(&Ws[k * 136 + q * 4]) = v;
            float4 g = *(const float4*)(Wg + (size_t)(k0 + k) * CC + q * 4);
            g.x = tf32r(g.x); g.y = tf32r(g.y); g.z = tf32r(g.z); g.w = tf32r(g.w);
            *(float4*)(&Wgs[k * 136 + q * 4]) = g;
        }
        __syncthreads();
        #pragma unroll
        for (int ks = 0; ks < 16; ks += 8) {
            uint32_t a[4][4], b[4][2], bg[4][2];
            #pragma unroll
            for (int mt = 0; mt < 4; mt++) {
                int rb = (warp_m * 64 + mt * 16 + lr) * 20 + ks + lc;
                a[mt][0] = __float_as_uint(Xs[rb]);
                a[mt][1] = __float_as_uint(Xs[rb + 8 * 20]);
                a[mt][2] = __float_as_uint(Xs[rb + 4]);
                a[mt][3] = __float_as_uint(Xs[rb + 8 * 20 + 4]);
            }
            #pragma unroll
            for (int nt = 0; nt < 4; nt++) {
                int nb = warp_n * 32 + nt * 8 + lr;
                b[nt][0]  = __float_as_uint(Ws[(ks + lc) * 136 + nb]);
                b[nt][1]  = __float_as_uint(Ws[(ks + 4 + lc) * 136 + nb]);
                bg[nt][0] = __float_as_uint(Wgs[(ks + lc) * 136 + nb]);
                bg[nt][1] = __float_as_uint(Wgs[(ks + 4 + lc) * 136 + nb]);
            }
            #pragma unroll
            for (int mt = 0; mt < 4; mt++)
                #pragma unroll
                for (int nt = 0; nt < 4; nt++) {
                    mma_tf32(acc[mt * 4 + nt], a[mt], b[nt]);
                    mma_tf32(accg[mt * 4 + nt], a[mt], bg[nt]);
                }
        }
        __syncthreads();
    }

    // epilogue: gate+mask into smem tile (64 rows per pass), then transposed c-major write
    float (*tile)[132] = (float (*)[132])sbuf;
    #pragma unroll
    for (int pass = 0; pass < 2; pass++) {
        if (warp_m == pass) {
            #pragma unroll
            for (int mt = 0; mt < 4; mt++) {
                #pragma unroll
                for (int nt = 0; nt < 4; nt++) {
                    int col = warp_n * 32 + nt * 8 + lc * 2;
                    float2 bb  = *(const float2*)(B + col);
                    float2 bbg = *(const float2*)(Bg + col);
                    #pragma unroll
                    for (int h = 0; h < 2; h++) {
                        int rl = mt * 16 + lr + h * 8;         // 0..63
                        int n = n0 + pass * 64 + rl;
                        float pm = mask[n >> 9] * mask[n & 511];
                        float vx = (acc[mt * 4 + nt][h * 2 + 0] + bb.x) * pm
                                 * sigf(accg[mt * 4 + nt][h * 2 + 0] + bbg.x);
                        float vy = (acc[mt * 4 + nt][h * 2 + 1] + bb.y) * pm
                                 * sigf(accg[mt * 4 + nt][h * 2 + 1] + bbg.y);
                        tile[rl][col]     = tf32r(vx);
                        tile[rl][col + 1] = tf32r(vy);
                    }
                }
            }
        }
        __syncthreads();
        {
            int c = tid >> 1, h = tid & 1;
            float* dst = dstT + (size_t)c * NROWS + n0 + pass * 64 + h * 32;
            #pragma unroll
            for (int q = 0; q < 8; q++) {
                int nb = h * 32 + q * 4;
                float4 v;
                v.x = tile[nb + 0][c]; v.y = tile[nb + 1][c];
                v.z = tile[nb + 2][c]; v.w = tile[nb + 3][c];
                *(float4*)(dst + q * 4) = v;
            }
        }
        __syncthreads();
    }
}

// ---------------- einsum via mma.sync tf32: per c-plane, D = Lt_c @ Rt_c^T ----------------
// Block 128i x 128j, 128 threads = 4 warps (2x2), warp tile 64x64, k-chunk 16.
__global__ void __launch_bounds__(128) einsum_mma()
{
    __shared__ float As[128 * 20];
    __shared__ float Bs[128 * 20];
    const int c  = blockIdx.z;
    const int i0 = blockIdx.x * 128;
    const int j0 = blockIdx.y * 128;
    const int tid  = threadIdx.x;
    const int wid  = tid >> 5;
    const int lane = tid & 31;
    const int warp_m = wid >> 1;
    const int warp_n = wid & 1;
    const int lr = lane >> 2;
    const int lc = lane & 3;

    const float* Ap = g_Lt + (size_t)c * NROWS + (size_t)i0 * 512;
    const float* Bp = g_Rt + (size_t)c * NROWS + (size_t)j0 * 512;

    float acc[32][4];
    #pragma unroll
    for (int t = 0; t < 32; t++)
        #pragma unroll
        for (int q = 0; q < 4; q++) acc[t][q] = 0.0f;

    for (int k0 = 0; k0 < LL; k0 += 16) {
        #pragma unroll
        for (int u = 0; u < 4; u++) {
            int idx = tid + u * 128;       // 0..511
            int r = idx >> 2;
            int q = idx & 3;
            *(float4*)(&As[r * 20 + q * 4]) = *(const float4*)(Ap + (size_t)r * 512 + k0 + q * 4);
            *(float4*)(&Bs[r * 20 + q * 4]) = *(const float4*)(Bp + (size_t)r * 512 + k0 + q * 4);
        }
        __syncthreads();
        #pragma unroll
        for (int ks = 0; ks < 16; ks += 8) {
            uint32_t a[4][4], b[8][2];
            #pragma unroll
            for (int mt = 0; mt < 4; mt++) {
                int rb = (warp_m * 64 + mt * 16 + lr) * 20 + ks + lc;
                a[mt][0] = __float_as_uint(As[rb]);
                a[mt][1] = __float_as_uint(As[rb + 8 * 20]);
                a[mt][2] = __float_as_uint(As[rb + 4]);
                a[mt][3] = __float_as_uint(As[rb + 8 * 20 + 4]);
            }
            #pragma unroll
            for (int nt = 0; nt < 8; nt++) {
                int rb = (warp_n * 64 + nt * 8 + lr) * 20 + ks + lc;
                b[nt][0] = __float_as_uint(Bs[rb]);
                b[nt][1] = __float_as_uint(Bs[rb + 4]);
            }
            #pragma unroll
            for (int mt = 0; mt < 4; mt++)
                #pragma unroll
                for (int nt = 0; nt < 8; nt++)
                    mma_tf32(acc[mt * 8 + nt], a[mt], b[nt]);
        }
        __syncthreads();
    }

    float* Op = g_Ot + (size_t)c * NROWS;
    #pragma unroll
    for (int mt = 0; mt < 4; mt++) {
        #pragma unroll
        for (int nt = 0; nt < 8; nt++) {
            int col = j0 + warp_n * 64 + nt * 8 + lc * 2;
            #pragma unroll
            for (int h = 0; h < 2; h++) {
                int row = i0 + warp_m * 64 + mt * 16 + lr + h * 8;
                float2 v;
                v.x = acc[mt * 8 + nt][h * 2 + 0];
                v.y = acc[mt * 8 + nt][h * 2 + 1];
                *(float2*)(Op + (size_t)row * 512 + col) = v;
            }
        }
    }
}

// ---------------- transpose + LayerNorm: Ot (c-major) -> X (n-major, normalized) ----------------
__global__ void __launch_bounds__(256) trans_ln(const float* __restrict__ scale,
                                                const float* __restrict__ bias,
                                                float* __restrict__ outX)
{
    __shared__ float tile[128][68];
    const int n0 = blockIdx.x * 64;
    const int t  = threadIdx.x;
    const int w  = t >> 5;
    const int l  = t & 31;

    #pragma unroll
    for (int p = 0; p < 8; p++) {
        int idx = t + p * 256;          // 0..2047 = 128 c x 16 float4
        int cc = idx >> 4;
        int q  = idx & 15;
        float4 v = *(const float4*)(g_Ot + (size_t)cc * NROWS + n0 + q * 4);
        tile[cc][q * 4 + 0] = v.x;
        tile[cc][q * 4 + 1] = v.y;
        tile[cc][q * 4 + 2] = v.z;
        tile[cc][q * 4 + 3] = v.w;
    }
    __syncthreads();

    float4 sc = *(const float4*)(scale + l * 4);
    float4 bi = *(const float4*)(bias  + l * 4);
    #pragma unroll
    for (int rr = 0; rr < 8; rr++) {
        int nl = w * 8 + rr;
        float v0 = tile[l * 4 + 0][nl];
        float v1 = tile[l * 4 + 1][nl];
        float v2 = tile[l * 4 + 2][nl];
        float v3 = tile[l * 4 + 3][nl];
        float s  = v0 + v1 + v2 + v3;
        float sq = v0*v0 + v1*v1 + v2*v2 + v3*v3;
        #pragma unroll
        for (int o = 16; o > 0; o >>= 1) {
            s  += __shfl_xor_sync(0xffffffffu, s,  o);
            sq += __shfl_xor_sync(0xffffffffu, sq, o);
        }
        float mean = s * (1.0f / CC);
        float var  = sq * (1.0f / CC) - mean * mean;
        float rstd = rsqrtf(var + 1e-5f);
        float4 r;
        r.x = (v0 - mean) * rstd * sc.x + bi.x;
        r.y = (v1 - mean) * rstd * sc.y + bi.y;
        r.z = (v2 - mean) * rstd * sc.z + bi.z;
        r.w = (v3 - mean) * rstd * sc.w + bi.w;
        *(float4*)(outX + (size_t)(n0 + nl) * CC + l * 4) = r;
    }
}

// ---------------- host launch ----------------
extern "C" void kernel_launch(void* const* d_in, const int* in_sizes, int n_in,
                              void* d_out, int out_size)
{
    const float* act         = (const float*)d_in[0];
    const float* mask        = (const float*)d_in[1];
    const float* norm_scale  = (const float*)d_in[2];
    const float* norm_bias   = (const float*)d_in[3];
    const float* w_left      = (const float*)d_in[4];
    const float* b_left      = (const float*)d_in[5];
    const float* w_right     = (const float*)d_in[6];
    const float* b_right     = (const float*)d_in[7];
    const float* w_lgate     = (const float*)d_in[8];
    const float* b_lgate     = (const float*)d_in[9];
    const float* w_rgate     = (const float*)d_in[10];
    const float* b_rgate     = (const float*)d_in[11];
    const float* fnorm_scale = (const float*)d_in[12];
    const float* fnorm_bias  = (const float*)d_in[13];
    const float* w_out       = (const float*)d_in[14];
    const float* b_out       = (const float*)d_in[15];
    const float* w_fgate     = (const float*)d_in[16];
    const float* b_fgate     = (const float*)d_in[17];

    float *X, *Fg;
    cudaGetSymbolAddress((void**)&X,  g_X);
    cudaGetSymbolAddress((void**)&Fg, g_Fg);

    // 1) x = LN(act)
    ln_kernel<<<NROWS / 8, 256>>>(act, norm_scale, norm_bias, X);

    // 2) fused projections + gates + mask -> Lt, Rt (c-major)
    proj_lr<<<dim3(NROWS / 128, 2), 256>>>(
        X, w_left, w_lgate, b_left, b_lgate,
        w_right, w_rgate, b_right, b_rgate, mask);

    // 3) final-gate projection: Fg = sigmoid(X @ w_fgate + b_fgate)
    gemm_mma_s<<<NROWS / 128, 256>>>(X, w_fgate, b_fgate, Fg, nullptr, 2);

    // 4) einsum on tensor cores -> Ot (c-major)
    einsum_mma<<<dim3(4, 4, CC), 128>>>();

    // 5) transpose back + LN -> X (n-major)
    trans_ln<<<NROWS / 64, 256>>>(fnorm_scale, fnorm_bias, X);

    // 6) output projection + final gate
    gemm_mma_s<<<NROWS / 128, 256>>>(X, w_out, b_out, (float*)d_out, Fg, 1);
}

// round 6
// speedup vs baseline: 1.2189x; 1.2189x over previous
#include <cuda_runtime.h>
#include <cstdint>
#include <math.h>

#define LL 512
#define CC 128
#define NROWS (LL*LL)   // 262144

// ---- scratch ----
__device__ float g_X[NROWS*CC];     // normalized input (n-major); reused for normalized einsum out
__device__ float g_Lt[CC*NROWS];    // left  gated+masked, c-major planes [c][i*512+k], tf32-rounded
__device__ float g_Rt[CC*NROWS];    // right gated+masked, c-major planes [c][j*512+k], tf32-rounded
__device__ float g_Fg[NROWS*CC];    // sigmoid(final gate), n-major
__device__ float g_Ot[CC*NROWS];    // einsum output, c-major planes [c][i*512+j]

__device__ __forceinline__ float sigf(float x) {
    return 1.0f / (1.0f + __expf(-x));
}
__device__ __forceinline__ float tf32r(float x) {
    uint32_t y;
    asm("cvt.rna.tf32.f32 %0, %1;" : "=r"(y) : "f"(x));
    return __uint_as_float(y);
}
__device__ __forceinline__ void mma_tf32(float* c, const uint32_t* a, const uint32_t* b) {
    asm volatile(
        "mma.sync.aligned.m16n8k8.row.col.f32.tf32.tf32.f32 "
        "{%0,%1,%2,%3}, {%4,%5,%6,%7}, {%8,%9}, {%0,%1,%2,%3};"
        : "+f"(c[0]), "+f"(c[1]), "+f"(c[2]), "+f"(c[3])
        : "r"(a[0]), "r"(a[1]), "r"(a[2]), "r"(a[3]), "r"(b[0]), "r"(b[1]));
}

// ---------------- LayerNorm: one warp per row of 128 ----------------
__global__ void ln_kernel(const float* __restrict__ in,
                          const float* __restrict__ scale,
                          const float* __restrict__ bias,
                          float* __restrict__ out)
{
    int warp = (blockIdx.x * blockDim.x + threadIdx.x) >> 5;
    int lane = threadIdx.x & 31;
    if (warp >= NROWS) return;
    const float4 v = *(const float4*)(in + (size_t)warp * CC + lane * 4);
    float s  = v.x + v.y + v.z + v.w;
    float sq = v.x*v.x + v.y*v.y + v.z*v.z + v.w*v.w;
    #pragma unroll
    for (int o = 16; o > 0; o >>= 1) {
        s  += __shfl_xor_sync(0xffffffffu, s,  o);
        sq += __shfl_xor_sync(0xffffffffu, sq, o);
    }
    float mean = s * (1.0f / CC);
    float var  = sq * (1.0f / CC) - mean * mean;
    float rstd = rsqrtf(var + 1e-5f);
    float4 sc = *(const float4*)(scale + lane * 4);
    float4 bi = *(const float4*)(bias  + lane * 4);
    float4 r;
    r.x = (v.x - mean) * rstd * sc.x + bi.x;
    r.y = (v.y - mean) * rstd * sc.y + bi.y;
    r.z = (v.z - mean) * rstd * sc.z + bi.z;
    r.w = (v.w - mean) * rstd * sc.w + bi.w;
    *(float4*)(out + (size_t)warp * CC + lane * 4) = r;
}

// ---------------- single-weight tf32 GEMM: (N x 128) @ (128 x 128) ----------------
// mode 1: out = (acc + bias) * gate ; mode 2: out = sigmoid(acc + bias)
__global__ void __launch_bounds__(256) gemm_mma_s(
    const float* __restrict__ X,
    const float* __restrict__ W,
    const float* __restrict__ B,
    float* __restrict__ out,
    const float* __restrict__ gate,
    int mode)
{
    __shared__ float Xs[128 * 20];
    __shared__ float Ws[16 * 136];
    const int r0   = blockIdx.x * 128;
    const int tid  = threadIdx.x;
    const int wid  = tid >> 5;
    const int lane = tid & 31;
    const int warp_m = wid >> 2;
    const int warp_n = wid & 3;
    const int lr = lane >> 2;
    const int lc = lane & 3;

    float acc[16][4];
    #pragma unroll
    for (int t = 0; t < 16; t++)
        #pragma unroll
        for (int q = 0; q < 4; q++) acc[t][q] = 0.0f;

    for (int k0 = 0; k0 < CC; k0 += 16) {
        #pragma unroll
        for (int u = 0; u < 2; u++) {
            int idx = tid + u * 256;
            int r = idx >> 2;
            int q = idx & 3;
            float4 v = *(const float4*)(X + (size_t)(r0 + r) * CC + k0 + q * 4);
            v.x = tf32r(v.x); v.y = tf32r(v.y); v.z = tf32r(v.z); v.w = tf32r(v.w);
            *(float4*)(&Xs[r * 20 + q * 4]) = v;
        }
        #pragma unroll
        for (int u = 0; u < 2; u++) {
            int idx = tid + u * 256;
            int k = idx >> 5;
            int q = idx & 31;
            float4 v = *(const float4*)(W + (size_t)(k0 + k) * CC + q * 4);
            v.x = tf32r(v.x); v.y = tf32r(v.y); v.z = tf32r(v.z); v.w = tf32r(v.w);
            *(float4*)(&Ws[k * 136 + q * 4]) = v;
        }
        __syncthreads();
        #pragma unroll
        for (int ks = 0; ks < 16; ks += 8) {
            uint32_t a[4][4], b[4][2];
            #pragma unroll
            for (int mt = 0; mt < 4; mt++) {
                int rb = (warp_m * 64 + mt * 16 + lr) * 20 + ks + lc;
                a[mt][0] = __float_as_uint(Xs[rb]);
                a[mt][1] = __float_as_uint(Xs[rb + 8 * 20]);
                a[mt][2] = __float_as_uint(Xs[rb + 4]);
                a[mt][3] = __float_as_uint(Xs[rb + 8 * 20 + 4]);
            }
            #pragma unroll
            for (int nt = 0; nt < 4; nt++) {
                int nb = warp_n * 32 + nt * 8 + lr;
                b[nt][0] = __float_as_uint(Ws[(ks + lc) * 136 + nb]);
                b[nt][1] = __float_as_uint(Ws[(ks + 4 + lc) * 136 + nb]);
            }
            #pragma unroll
            for (int mt = 0; mt < 4; mt++)
                #pragma unroll
                for (int nt = 0; nt < 4; nt++)
                    mma_tf32(acc[mt * 4 + nt], a[mt], b[nt]);
        }
        __syncthreads();
    }

    #pragma unroll
    for (int mt = 0; mt < 4; mt++) {
        #pragma unroll
        for (int nt = 0; nt < 4; nt++) {
            int col = warp_n * 32 + nt * 8 + lc * 2;
            float2 bb = *(const float2*)(B + col);
            #pragma unroll
            for (int h = 0; h < 2; h++) {
                int row = r0 + warp_m * 64 + mt * 16 + lr + h * 8;
                float2 v;
                v.x = acc[mt * 4 + nt][h * 2 + 0] + bb.x;
                v.y = acc[mt * 4 + nt][h * 2 + 1] + bb.y;
                if (mode == 1) {
                    float2 gv = *(const float2*)(gate + (size_t)row * CC + col);
                    v.x *= gv.x; v.y *= gv.y;
                } else if (mode == 2) {
                    v.x = sigf(v.x); v.y = sigf(v.y);
                }
                *(float2*)(out + (size_t)row * CC + col) = v;
            }
        }
    }
}

// ---------------- fused projection + gate + mask + c-major transpose ----------------
// grid.y in 0..3: sel = y>>1 (0=L,1=R), half = y&1 (which 64-col slice).
// Block: 128 rows x 64 cols, both W and Wg. Warp tile 64x16 each.
__global__ void __launch_bounds__(256) proj_lr(
    const float* __restrict__ X,
    const float* __restrict__ w_l,  const float* __restrict__ w_lg,
    const float* __restrict__ b_l,  const float* __restrict__ b_lg,
    const float* __restrict__ w_r,  const float* __restrict__ w_rg,
    const float* __restrict__ b_r,  const float* __restrict__ b_rg,
    const float* __restrict__ mask)
{
    __shared__ float sbuf[128 * 68];   // epilogue tile 128n x 64c (stride 68); mainloop uses 4864
    float* Xs  = sbuf;                 // 128*20 = 2560
    float* Ws  = sbuf + 2560;          // 16*72 = 1152
    float* Wgs = sbuf + 2560 + 1152;   // 16*72

    const int sel  = blockIdx.y >> 1;
    const int half = blockIdx.y & 1;
    const float* W  = (sel ? w_r  : w_l)  + half * 64;
    const float* Wg = (sel ? w_rg : w_lg) + half * 64;
    const float* B  = (sel ? b_r  : b_l)  + half * 64;
    const float* Bg = (sel ? b_rg : b_lg) + half * 64;
    float* dstT = (sel ? g_Rt : g_Lt) + (size_t)(half * 64) * NROWS;

    const int n0   = blockIdx.x * 128;
    const int tid  = threadIdx.x;
    const int wid  = tid >> 5;
    const int lane = tid & 31;
    const int warp_m = wid >> 2;       // 0..1
    const int warp_n = wid & 3;        // 0..3 (16 cols each)
    const int lr = lane >> 2;
    const int lc = lane & 3;

    float acc[8][4], accg[8][4];
    #pragma unroll
    for (int t = 0; t < 8; t++)
        #pragma unroll
        for (int q = 0; q < 4; q++) { acc[t][q] = 0.0f; accg[t][q] = 0.0f; }

    for (int k0 = 0; k0 < CC; k0 += 16) {
        // X tile: 128 rows x 16 k
        #pragma unroll
        for (int u = 0; u < 2; u++) {
            int idx = tid + u * 256;
            int r = idx >> 2;
            int q = idx & 3;
            float4 v = *(const float4*)(X + (size_t)(n0 + r) * CC + k0 + q * 4);
            v.x = tf32r(v.x); v.y = tf32r(v.y); v.z = tf32r(v.z); v.w = tf32r(v.w);
            *(float4*)(&Xs[r * 20 + q * 4]) = v;
        }
        // W, Wg chunks: 16 k x 64 n  (256 threads cover 16x16 float4)
        {
            int k = tid >> 4;
            int q = tid & 15;
            float4 v = *(const float4*)(W + (size_t)(k0 + k) * CC + q * 4);
            v.x = tf32r(v.x); v.y = tf32r(v.y); v.z = tf32r(v.z); v.w = tf32r(v.w);
            *(float4*)(&Ws[k * 72 + q * 4]) = v;
            float4 g = *(const float4*)(Wg + (size_t)(k0 + k) * CC + q * 4);
            g.x = tf32r(g.x); g.y = tf32r(g.y); g.z = tf32r(g.z); g.w = tf32r(g.w);
            *(float4*)(&Wgs[k * 72 + q * 4]) = g;
        }
        __syncthreads();
        #pragma unroll
        for (int ks = 0; ks < 16; ks += 8) {
            uint32_t a[4][4], b[2][2], bg[2][2];
            #pragma unroll
            for (int mt = 0; mt < 4; mt++) {
                int rb = (warp_m * 64 + mt * 16 + lr) * 20 + ks + lc;
                a[mt][0] = __float_as_uint(Xs[rb]);
                a[mt][1] = __float_as_uint(Xs[rb + 8 * 20]);
                a[mt][2] = __float_as_uint(Xs[rb + 4]);
                a[mt][3] = __float_as_uint(Xs[rb + 8 * 20 + 4]);
            }
            #pragma unroll
            for (int nt = 0; nt < 2; nt++) {
                int nb = warp_n * 16 + nt * 8 + lr;
                b[nt][0]  = __float_as_uint(Ws[(ks + lc) * 72 + nb]);
                b[nt][1]  = __float_as_uint(Ws[(ks + 4 + lc) * 72 + nb]);
                bg[nt][0] = __float_as_uint(Wgs[(ks + lc) * 72 + nb]);
                bg[nt][1] = __float_as_uint(Wgs[(ks + 4 + lc) * 72 + nb]);
            }
            #pragma unroll
            for (int mt = 0; mt < 4; mt++)
                #pragma unroll
                for (int nt = 0; nt < 2; nt++) {
                    mma_tf32(acc[mt * 2 + nt], a[mt], b[nt]);
                    mma_tf32(accg[mt * 2 + nt], a[mt], bg[nt]);
                }
        }
        __syncthreads();
    }

    // epilogue: gate+mask into full 128x64 smem tile, then transposed c-major write
    float (*tile)[68] = (float (*)[68])sbuf;
    #pragma unroll
    for (int mt = 0; mt < 4; mt++) {
        #pragma unroll
        for (int nt = 0; nt < 2; nt++) {
            int col = warp_n * 16 + nt * 8 + lc * 2;
            float2 bb  = *(const float2*)(B + col);
            float2 bbg = *(const float2*)(Bg + col);
            #pragma unroll
            for (int h = 0; h < 2; h++) {
                int rl = warp_m * 64 + mt * 16 + lr + h * 8;   // 0..127
                int n = n0 + rl;
                float pm = mask[n >> 9] * mask[n & 511];
                float vx = (acc[mt * 2 + nt][h * 2 + 0] + bb.x) * pm
                         * sigf(accg[mt * 2 + nt][h * 2 + 0] + bbg.x);
                float vy = (acc[mt * 2 + nt][h * 2 + 1] + bb.y) * pm
                         * sigf(accg[mt * 2 + nt][h * 2 + 1] + bbg.y);
                tile[rl][col]     = tf32r(vx);
                tile[rl][col + 1] = tf32r(vy);
            }
        }
    }
    __syncthreads();
    {
        int c = tid >> 2;          // 0..63
        int h = tid & 3;           // 0..3 -> 32-row quarter
        float* dst = dstT + (size_t)c * NROWS + n0 + h * 32;
        #pragma unroll
        for (int q = 0; q < 8; q++) {
            int nb = h * 32 + q * 4;
            float4 v;
            v.x = tile[nb + 0][c]; v.y = tile[nb + 1][c];
            v.z = tile[nb + 2][c]; v.w = tile[nb + 3][c];
            *(float4*)(dst + q * 4) = v;
        }
    }
}

// ---------------- einsum via mma.sync tf32: per c-plane, D = Lt_c @ Rt_c^T ----------------
// Block 128i x 128j, 128 threads = 4 warps (2x2), warp tile 64x64, k-chunk 16.
__global__ void __launch_bounds__(128) einsum_mma()
{
    __shared__ float As[128 * 20];
    __shared__ float Bs[128 * 20];
    const int c  = blockIdx.z;
    const int i0 = blockIdx.x * 128;
    const int j0 = blockIdx.y * 128;
    const int tid  = threadIdx.x;
    const int wid  = tid >> 5;
    const int lane = tid & 31;
    const int warp_m = wid >> 1;
    const int warp_n = wid & 1;
    const int lr = lane >> 2;
    const int lc = lane & 3;

    const float* Ap = g_Lt + (size_t)c * NROWS + (size_t)i0 * 512;
    const float* Bp = g_Rt + (size_t)c * NROWS + (size_t)j0 * 512;

    float acc[32][4];
    #pragma unroll
    for (int t = 0; t < 32; t++)
        #pragma unroll
        for (int q = 0; q < 4; q++) acc[t][q] = 0.0f;

    for (int k0 = 0; k0 < LL; k0 += 16) {
        #pragma unroll
        for (int u = 0; u < 4; u++) {
            int idx = tid + u * 128;       // 0..511
            int r = idx >> 2;
            int q = idx & 3;
            *(float4*)(&As[r * 20 + q * 4]) = *(const float4*)(Ap + (size_t)r * 512 + k0 + q * 4);
            *(float4*)(&Bs[r * 20 + q * 4]) = *(const float4*)(Bp + (size_t)r * 512 + k0 + q * 4);
        }
        __syncthreads();
        #pragma unroll
        for (int ks = 0; ks < 16; ks += 8) {
            uint32_t a[4][4], b[8][2];
            #pragma unroll
            for (int mt = 0; mt < 4; mt++) {
                int rb = (warp_m * 64 + mt * 16 + lr) * 20 + ks + lc;
                a[mt][0] = __float_as_uint(As[rb]);
                a[mt][1] = __float_as_uint(As[rb + 8 * 20]);
                a[mt][2] = __float_as_uint(As[rb + 4]);
                a[mt][3] = __float_as_uint(As[rb + 8 * 20 + 4]);
            }
            #pragma unroll
            for (int nt = 0; nt < 8; nt++) {
                int rb = (warp_n * 64 + nt * 8 + lr) * 20 + ks + lc;
                b[nt][0] = __float_as_uint(Bs[rb]);
                b[nt][1] = __float_as_uint(Bs[rb + 4]);
            }
            #pragma unroll
            for (int mt = 0; mt < 4; mt++)
                #pragma unroll
                for (int nt = 0; nt < 8; nt++)
                    mma_tf32(acc[mt * 8 + nt], a[mt], b[nt]);
        }
        __syncthreads();
    }

    float* Op = g_Ot + (size_t)c * NROWS;
    #pragma unroll
    for (int mt = 0; mt < 4; mt++) {
        #pragma unroll
        for (int nt = 0; nt < 8; nt++) {
            int col = j0 + warp_n * 64 + nt * 8 + lc * 2;
            #pragma unroll
            for (int h = 0; h < 2; h++) {
                int row = i0 + warp_m * 64 + mt * 16 + lr + h * 8;
                float2 v;
                v.x = acc[mt * 8 + nt][h * 2 + 0];
                v.y = acc[mt * 8 + nt][h * 2 + 1];
                *(float2*)(Op + (size_t)row * 512 + col) = v;
            }
        }
    }
}

// ---------------- transpose + LayerNorm: Ot (c-major) -> X (n-major, normalized) ----------------
__global__ void __launch_bounds__(256) trans_ln(const float* __restrict__ scale,
                                                const float* __restrict__ bias,
                                                float* __restrict__ outX)
{
    __shared__ float tile[128][68];
    const int n0 = blockIdx.x * 64;
    const int t  = threadIdx.x;
    const int w  = t >> 5;
    const int l  = t & 31;

    #pragma unroll
    for (int p = 0; p < 8; p++) {
        int idx = t + p * 256;          // 0..2047 = 128 c x 16 float4
        int cc = idx >> 4;
        int q  = idx & 15;
        float4 v = *(const float4*)(g_Ot + (size_t)cc * NROWS + n0 + q * 4);
        tile[cc][q * 4 + 0] = v.x;
        tile[cc][q * 4 + 1] = v.y;
        tile[cc][q * 4 + 2] = v.z;
        tile[cc][q * 4 + 3] = v.w;
    }
    __syncthreads();

    float4 sc = *(const float4*)(scale + l * 4);
    float4 bi = *(const float4*)(bias  + l * 4);
    #pragma unroll
    for (int rr = 0; rr < 8; rr++) {
        int nl = w * 8 + rr;
        float v0 = tile[l * 4 + 0][nl];
        float v1 = tile[l * 4 + 1][nl];
        float v2 = tile[l * 4 + 2][nl];
        float v3 = tile[l * 4 + 3][nl];
        float s  = v0 + v1 + v2 + v3;
        float sq = v0*v0 + v1*v1 + v2*v2 + v3*v3;
        #pragma unroll
        for (int o = 16; o > 0; o >>= 1) {
            s  += __shfl_xor_sync(0xffffffffu, s,  o);
            sq += __shfl_xor_sync(0xffffffffu, sq, o);
        }
        float mean = s * (1.0f / CC);
        float var  = sq * (1.0f / CC) - mean * mean;
        float rstd = rsqrtf(var + 1e-5f);
        float4 r;
        r.x = (v0 - mean) * rstd * sc.x + bi.x;
        r.y = (v1 - mean) * rstd * sc.y + bi.y;
        r.z = (v2 - mean) * rstd * sc.z + bi.z;
        r.w = (v3 - mean) * rstd * sc.w + bi.w;
        *(float4*)(outX + (size_t)(n0 + nl) * CC + l * 4) = r;
    }
}

// ---------------- host launch ----------------
extern "C" void kernel_launch(void* const* d_in, const int* in_sizes, int n_in,
                              void* d_out, int out_size)
{
    const float* act         = (const float*)d_in[0];
    const float* mask        = (const float*)d_in[1];
    const float* norm_scale  = (const float*)d_in[2];
    const float* norm_bias   = (const float*)d_in[3];
    const float* w_left      = (const float*)d_in[4];
    const float* b_left      = (const float*)d_in[5];
    const float* w_right     = (const float*)d_in[6];
    const float* b_right     = (const float*)d_in[7];
    const float* w_lgate     = (const float*)d_in[8];
    const float* b_lgate     = (const float*)d_in[9];
    const float* w_rgate     = (const float*)d_in[10];
    const float* b_rgate     = (const float*)d_in[11];
    const float* fnorm_scale = (const float*)d_in[12];
    const float* fnorm_bias  = (const float*)d_in[13];
    const float* w_out       = (const float*)d_in[14];
    const float* b_out       = (const float*)d_in[15];
    const float* w_fgate     = (const float*)d_in[16];
    const float* b_fgate     = (const float*)d_in[17];

    float *X, *Fg;
    cudaGetSymbolAddress((void**)&X,  g_X);
    cudaGetSymbolAddress((void**)&Fg, g_Fg);

    // 1) x = LN(act)
    ln_kernel<<<NROWS / 8, 256>>>(act, norm_scale, norm_bias, X);

    // 2) fused projections + gates + mask -> Lt, Rt (c-major)
    proj_lr<<<dim3(NROWS / 128, 4), 256>>>(
        X, w_left, w_lgate, b_left, b_lgate,
        w_right, w_rgate, b_right, b_rgate, mask);

    // 3) final-gate projection: Fg = sigmoid(X @ w_fgate + b_fgate)
    gemm_mma_s<<<NROWS / 128, 256>>>(X, w_fgate, b_fgate, Fg, nullptr, 2);

    // 4) einsum on tensor cores -> Ot (c-major)
    einsum_mma<<<dim3(4, 4, CC), 128>>>();

    // 5) transpose back + LN -> X (n-major)
    trans_ln<<<NROWS / 64, 256>>>(fnorm_scale, fnorm_bias, X);

    // 6) output projection + final gate
    gemm_mma_s<<<NROWS / 128, 256>>>(X, w_out, b_out, (float*)d_out, Fg, 1);
}